// round 7
// baseline (speedup 1.0000x reference)
#include <cuda_runtime.h>
#include <cuda_bf16.h>
#include <math.h>
#include <stdint.h>

#define Bv 8
#define Sv 512
#define Tv 64
#define Dv 512
#define Hv 8
#define Vv 32000
#define EVv 2048
#define VTv 34048

#define FMINF (-3.402823466e38f)
#define LOG_EPS (-15.9423847198486328125f)   /* logf(2^-23) */

// ---------------- scratch ----------------
__device__ __align__(16) float g_k[Bv*Sv*Dv];         // 8 MB
__device__ __align__(16) float g_q[Bv*Tv*Dv];         // 1 MB
__device__ __align__(16) float g_scores[Bv*Hv*Tv*Sv]; // 8 MB
__device__ __align__(16) float g_attn[Bv*Tv*Sv];      // 1 MB
__device__ __align__(16) float g_maskf[Bv*Sv];        // 0 or -inf
__device__ float g_logcp[Bv*Tv];
__device__ float g_log1mcp[Bv*Tv];
__device__ float g_lse[Bv*Tv];
__device__ int   g_canon[Bv*Sv];

// bf16 split copies (activations stacked: rows 0..4095 = src, 4096..4607 = tgt)
__device__ __align__(16) __nv_bfloat16 g_a_hi[4608*512];
__device__ __align__(16) __nv_bfloat16 g_a_lo[4608*512];
// transposed weights: slice 0 = w_k^T [n][k], slice 1 = w_q^T
__device__ __align__(16) __nv_bfloat16 g_wt_hi[2*512*512];
__device__ __align__(16) __nv_bfloat16 g_wt_lo[2*512*512];

// ---------------- helpers ----------------
__device__ __forceinline__ float lae(float a, float b) {
    float m = fmaxf(a, b);
    return m + log1pf(__expf(-fabsf(a - b)));
}

// fast exp on the FMA pipe (poly 2^f; rel err ~5e-5)
__device__ __forceinline__ float expp(float x) {
    x = fmaxf(x, -80.0f);
    float y = x * 1.44269504f;
    float n = rintf(y);
    float f = y - n;
    float p = 0.00961813f;
    p = fmaf(p, f, 0.05550411f);
    p = fmaf(p, f, 0.24022651f);
    p = fmaf(p, f, 0.69314718f);
    p = fmaf(p, f, 1.0f);
    float s = __int_as_float(((int)n + 127) << 23);
    return p * s;
}

__device__ __forceinline__ uint32_t smem_u32(const void* p) {
    uint32_t a;
    asm("{ .reg .u64 t; cvta.to.shared.u64 t, %1; cvt.u32.u64 %0, t; }" : "=r"(a) : "l"(p));
    return a;
}
__device__ __forceinline__ void ldsm4(uint32_t* r, uint32_t addr) {
    asm volatile("ldmatrix.sync.aligned.m8n8.x4.shared.b16 {%0,%1,%2,%3}, [%4];"
                 : "=r"(r[0]), "=r"(r[1]), "=r"(r[2]), "=r"(r[3]) : "r"(addr));
}
__device__ __forceinline__ void mma_bf16(float* d, const uint32_t* a, const uint32_t* b) {
    asm volatile(
        "mma.sync.aligned.m16n8k16.row.col.f32.bf16.bf16.f32 "
        "{%0,%1,%2,%3}, {%4,%5,%6,%7}, {%8,%9}, {%0,%1,%2,%3};"
        : "+f"(d[0]), "+f"(d[1]), "+f"(d[2]), "+f"(d[3])
        : "r"(a[0]), "r"(a[1]), "r"(a[2]), "r"(a[3]), "r"(b[0]), "r"(b[1]));
}
__device__ __forceinline__ void cpa16(uint32_t s, const void* g) {
    asm volatile("cp.async.cg.shared.global [%0], [%1], 16;" :: "r"(s), "l"(g));
}

// ---------------- K1: prep_all = canon+mask / copygate / conv_a / conv_w ----------------
__global__ __launch_bounds__(512)
void prep_all_kernel(const void* __restrict__ pad,
                     const int* __restrict__ ids,
                     const float* __restrict__ tgt,
                     const float* __restrict__ wc,
                     const float* __restrict__ bc,
                     const float* __restrict__ src,
                     const float* __restrict__ wk,
                     const float* __restrict__ wq) {
    int bid = blockIdx.x;
    int tid = threadIdx.x;

    if (bid < 8) {
        // canonical representative + float mask for batch b
        int b = bid;
        __shared__ int sid[512];
        __shared__ int bad;
        if (tid == 0) bad = 0;
        sid[tid] = ids[b * Sv + tid];
        __syncthreads();
        // local dtype sniff (first 4096 bytes — safe under bool or int layout)
        const unsigned* w = (const unsigned*)pad;
        for (int i = tid; i < 1024; i += 512)
            if (w[i] > 1u) atomicOr(&bad, 1);
        // canon scan
        int my = sid[tid];
        bool canon = true;
        for (int j = 0; j < tid; j++)
            if (sid[j] == my) { canon = false; break; }
        int cnt = 0;
        if (canon)
            for (int j = tid + 1; j < Sv; j++) cnt += (sid[j] == my);
        g_canon[b * Sv + tid] = canon ? cnt : -1;
        __syncthreads();
        bool isint = (bad == 0);
        int idx = b * Sv + tid;
        bool p = isint ? (((const int*)pad)[idx] != 0)
                       : (((const unsigned char*)pad)[idx] != 0);
        g_maskf[idx] = p ? -INFINITY : 0.0f;
        return;
    }
    if (bid < 520) {
        // copy gate
        int bt = bid - 8;
        float acc = tgt[(size_t)bt * Dv + tid] * wc[tid];
        for (int off = 16; off > 0; off >>= 1)
            acc += __shfl_xor_sync(0xFFFFFFFF, acc, off);
        __shared__ float sred[16];
        int warp = tid >> 5, lane = tid & 31;
        if (lane == 0) sred[warp] = acc;
        __syncthreads();
        if (tid == 0) {
            float z = bc[0];
            for (int i = 0; i < 16; i++) z += sred[i];
            float cp = 1.f / (1.f + expf(-z));
            g_logcp[bt]   = logf(cp);
            g_log1mcp[bt] = logf(1.f - cp);
        }
        return;
    }
    if (bid < 1672) {
        // convert activations: fp32 -> bf16 hi/lo
        int q = (bid - 520) * 512 + tid;     // float4 index 0..589823
        int row = q >> 7;
        int c4  = (q & 127) * 4;
        float4 v = (row < 4096)
            ? *(const float4*)&src[(size_t)row * 512 + c4]
            : *(const float4*)&tgt[(size_t)(row - 4096) * 512 + c4];
        float xs[4] = {v.x, v.y, v.z, v.w};
        unsigned short h[4], l[4];
#pragma unroll
        for (int i = 0; i < 4; i++) {
            __nv_bfloat16 hb = __float2bfloat16(xs[i]);
            float lo = xs[i] - __bfloat162float(hb);
            h[i] = __bfloat16_as_ushort(hb);
            l[i] = __bfloat16_as_ushort(__float2bfloat16(lo));
        }
        uint2 H = {(unsigned)h[0] | ((unsigned)h[1] << 16), (unsigned)h[2] | ((unsigned)h[3] << 16)};
        uint2 L = {(unsigned)l[0] | ((unsigned)l[1] << 16), (unsigned)l[2] | ((unsigned)l[3] << 16)};
        *(uint2*)&g_a_hi[(size_t)row * 512 + c4] = H;
        *(uint2*)&g_a_lo[(size_t)row * 512 + c4] = L;
        return;
    }
    // transpose + convert weights
    {
        int bid2 = bid - 1672;               // 0..511
        int z = bid2 >> 8;
        const float* W = z ? wq : wk;
        int r = bid2 & 255;
        int n0 = (r & 15) * 32, k0 = (r >> 4) * 32;
        __shared__ float tile[32][33];
        int tx = tid & 31, ty = tid >> 5;    // 512 = 32 x 16
#pragma unroll
        for (int i = 0; i < 2; i++)
            tile[ty + i * 16][tx] = W[(size_t)(k0 + ty + i * 16) * 512 + n0 + tx];
        __syncthreads();
#pragma unroll
        for (int i = 0; i < 2; i++) {
            int n = n0 + ty + i * 16;
            int k = k0 + tx;
            float x = tile[tx][ty + i * 16];
            __nv_bfloat16 hb = __float2bfloat16(x);
            float lo = x - __bfloat162float(hb);
            size_t o = (size_t)z * 262144 + (size_t)n * 512 + k;
            g_wt_hi[o] = hb;
            g_wt_lo[o] = __float2bfloat16(lo);
        }
    }
}

// ---------------- K-lse (stream 2): S = sum exp(logits row); lse -> g_lse ----------------
__global__ __launch_bounds__(512)
void lse_sum_kernel(const float* __restrict__ logits) {
    int bt = blockIdx.x;
    int tid = threadIdx.x;
    const float4* row = (const float4*)(logits + (size_t)bt * Vv);
    __shared__ float ssum[16];
    int warp = tid >> 5, lane = tid & 31;

    float s = 0.f;
    for (int i = tid; i < Vv / 4; i += 512) {
        float4 v = row[i];
        s += expp(v.x) + expp(v.y) + expp(v.z) + expp(v.w);
    }
    for (int off = 16; off > 0; off >>= 1)
        s += __shfl_xor_sync(0xFFFFFFFF, s, off);
    if (lane == 0) ssum[warp] = s;
    __syncthreads();
    if (tid == 0) {
        float S = ssum[0];
#pragma unroll
        for (int i = 1; i < 16; i++) S += ssum[i];
        g_lse[bt] = __logf(S);
    }
}

// ---------------- K2: HMMA dual GEMM, BM=128 BN=128, 3-stage cp.async, K_CHUNK=32 ----------------
#define A_HI 0
#define A_LO 10240
#define B_HI 20480
#define B_LO 30720
#define STG_SZ 40960
#define GSM (3 * STG_SZ)

__global__ __launch_bounds__(256)
void gemm_mma_kernel(const float* __restrict__ b_k, const float* __restrict__ b_q) {
    extern __shared__ __align__(16) char sm[];
    int tid = threadIdx.x;
    int lane = tid & 31;
    int wid = tid >> 5;
    int wm = wid & 1, wn = wid >> 1;   // 2m x 4n, warp tile 64x32

    int yb = blockIdx.y;
    bool isQ = (yb >= 32);
    int arow0 = isQ ? 4096 + (yb - 32) * 128 : yb * 128;
    int orow0 = isQ ? (yb - 32) * 128 : yb * 128;
    float* C = isQ ? g_q : g_k;
    const float* bias = isQ ? b_q : b_k;
    int n0 = blockIdx.x * 128;
    size_t wtb = (isQ ? (size_t)262144 : 0) + (size_t)n0 * 512;

    uint32_t sbase = smem_u32(sm);

    auto issue_chunk = [&](int kc, int st) {
        uint32_t sb = sbase + st * STG_SZ;
#pragma unroll
        for (int i = 0; i < 2; i++) {
            int idx = tid + i * 256;
            int r = idx >> 2, c = idx & 3;
            uint32_t d = (uint32_t)(r * 80 + c * 16);
            size_t ga = (size_t)(arow0 + r) * 512 + kc * 32 + c * 8;
            cpa16(sb + A_HI + d, &g_a_hi[ga]);
            cpa16(sb + A_LO + d, &g_a_lo[ga]);
            size_t gb = wtb + (size_t)r * 512 + kc * 32 + c * 8;
            cpa16(sb + B_HI + d, &g_wt_hi[gb]);
            cpa16(sb + B_LO + d, &g_wt_lo[gb]);
        }
        asm volatile("cp.async.commit_group;" ::: "memory");
    };

    int a_row = (lane & 7) + ((lane >> 3) & 1) * 8;
    int a_k8  = (lane >> 4) * 8;
    int b_row = (lane & 7) + (lane >> 4) * 8;
    int b_k8  = ((lane >> 3) & 1) * 8;

    float acc[4][4][4] = {};

    issue_chunk(0, 0);
    issue_chunk(1, 1);

#pragma unroll 1
    for (int kc = 0; kc < 16; kc++) {
        if (kc < 14) asm volatile("cp.async.wait_group 1;" ::: "memory");
        else         asm volatile("cp.async.wait_group 0;" ::: "memory");
        __syncthreads();
        if (kc + 2 < 16) issue_chunk(kc + 2, (kc + 2) % 3);

        uint32_t cb = sbase + (uint32_t)((kc % 3) * STG_SZ);
        uint32_t aB = cb + A_HI + (uint32_t)(wm * 64 + a_row) * 80 + a_k8 * 2;
        uint32_t bB = cb + B_HI + (uint32_t)(wn * 32 + b_row) * 80 + b_k8 * 2;

#pragma unroll
        for (int ks = 0; ks < 2; ks++) {
            uint32_t bh0[4], bh1[4], bl0[4], bl1[4];
            uint32_t ba = bB + ks * 32;
            ldsm4(bh0, ba);
            ldsm4(bh1, ba + 16 * 80);
            ldsm4(bl0, ba + (B_LO - B_HI));
            ldsm4(bl1, ba + (B_LO - B_HI) + 16 * 80);
#pragma unroll
            for (int mt = 0; mt < 4; mt++) {
                uint32_t ah[4], al[4];
                uint32_t aa = aB + (uint32_t)(mt * 16) * 80 + ks * 32;
                ldsm4(ah, aa);
                ldsm4(al, aa + (A_LO - A_HI));
                mma_bf16(acc[mt][0], ah, bh0);
                mma_bf16(acc[mt][0], ah, bl0);
                mma_bf16(acc[mt][0], al, bh0);
                mma_bf16(acc[mt][1], ah, bh0 + 2);
                mma_bf16(acc[mt][1], ah, bl0 + 2);
                mma_bf16(acc[mt][1], al, bh0 + 2);
                mma_bf16(acc[mt][2], ah, bh1);
                mma_bf16(acc[mt][2], ah, bl1);
                mma_bf16(acc[mt][2], al, bh1);
                mma_bf16(acc[mt][3], ah, bh1 + 2);
                mma_bf16(acc[mt][3], ah, bl1 + 2);
                mma_bf16(acc[mt][3], al, bh1 + 2);
            }
        }
    }

    // epilogue
    int g = lane >> 2, t4 = lane & 3;
#pragma unroll
    for (int mt = 0; mt < 4; mt++) {
#pragma unroll
        for (int nt = 0; nt < 4; nt++) {
            int col = n0 + wn * 32 + nt * 8 + t4 * 2;
            float2 bb = *(const float2*)&bias[col];
            int row0 = orow0 + wm * 64 + mt * 16 + g;
            float2 v0 = {acc[mt][nt][0] + bb.x, acc[mt][nt][1] + bb.y};
            float2 v1 = {acc[mt][nt][2] + bb.x, acc[mt][nt][3] + bb.y};
            *(float2*)&C[(size_t)row0 * 512 + col] = v0;
            *(float2*)&C[(size_t)(row0 + 8) * 512 + col] = v1;
        }
    }
}

// ---------------- K3: scores — register-tiled 64x512x64 SGEMM per (b,h,squarter) ----------------
__global__ __launch_bounds__(128)
void scores_kernel() {
    __shared__ __align__(16) float kT[64][128];  // [d][s]
    __shared__ __align__(16) float qT[64][72];   // [d][t], padded
    int bh = blockIdx.x;
    int b = bh >> 3, h = bh & 7;
    int s0 = blockIdx.y * 128;
    int tid = threadIdx.x;

    {
        int s = tid;
        const float* kp = &g_k[((size_t)(b * Sv + s0 + s)) * Dv + h * 64];
#pragma unroll
        for (int j = 0; j < 16; j++) {
            float4 v = *(const float4*)&kp[j * 4];
            kT[j * 4 + 0][s] = v.x;
            kT[j * 4 + 1][s] = v.y;
            kT[j * 4 + 2][s] = v.z;
            kT[j * 4 + 3][s] = v.w;
        }
    }
    {
        int t = tid & 63, dh = tid >> 6;
        const float* qp = &g_q[((size_t)(b * Tv + t)) * Dv + h * 64 + dh * 32];
#pragma unroll
        for (int j = 0; j < 8; j++) {
            float4 v = *(const float4*)&qp[j * 4];
            int d = dh * 32 + j * 4;
            qT[d + 0][t] = v.x;
            qT[d + 1][t] = v.y;
            qT[d + 2][t] = v.z;
            qT[d + 3][t] = v.w;
        }
    }
    __syncthreads();

    int tx = tid & 15, ty = tid >> 4;
    float acc[8][8] = {};
#pragma unroll
    for (int kk = 0; kk < 64; kk++) {
        float4 a0 = *(const float4*)&qT[kk][ty * 8];
        float4 a1 = *(const float4*)&qT[kk][ty * 8 + 4];
        float4 b0 = *(const float4*)&kT[kk][tx * 8];
        float4 b1 = *(const float4*)&kT[kk][tx * 8 + 4];
        float av[8] = {a0.x, a0.y, a0.z, a0.w, a1.x, a1.y, a1.z, a1.w};
        float bv[8] = {b0.x, b0.y, b0.z, b0.w, b1.x, b1.y, b1.z, b1.w};
#pragma unroll
        for (int i = 0; i < 8; i++)
#pragma unroll
            for (int j = 0; j < 8; j++)
                acc[i][j] += av[i] * bv[j];
    }

    float* op = &g_scores[(((size_t)(b * Hv + h)) * Tv) * Sv + s0];
#pragma unroll
    for (int i = 0; i < 8; i++) {
        int t = ty * 8 + i;
#pragma unroll
        for (int j = 0; j < 2; j++) {
            float4 o = {acc[i][j * 4 + 0] * 0.125f, acc[i][j * 4 + 1] * 0.125f,
                        acc[i][j * 4 + 2] * 0.125f, acc[i][j * 4 + 3] * 0.125f};
            *(float4*)&op[(size_t)t * Sv + tx * 8 + j * 4] = o;
        }
    }
}

// ---------------- K4: masked softmax per head + mean over heads (float4) ----------------
__global__ __launch_bounds__(256)
void softmax_mean_kernel() {
    int bt = blockIdx.x;
    int b = bt / Tv, t = bt % Tv;
    int warp = threadIdx.x >> 5, lane = threadIdx.x & 31;

    __shared__ float probs[8][512];

    const float* sc = &g_scores[(((size_t)b * Hv + warp) * Tv + t) * Sv];
    const float* mk = &g_maskf[b * Sv];

    float vals[16];
    float m = -INFINITY;
#pragma unroll
    for (int i = 0; i < 4; i++) {
        int s = i * 128 + lane * 4;
        float4 v = *(const float4*)&sc[s];
        float4 q = *(const float4*)&mk[s];
        v.x += q.x; v.y += q.y; v.z += q.z; v.w += q.w;
        vals[i * 4 + 0] = v.x; vals[i * 4 + 1] = v.y;
        vals[i * 4 + 2] = v.z; vals[i * 4 + 3] = v.w;
        m = fmaxf(m, fmaxf(fmaxf(v.x, v.y), fmaxf(v.z, v.w)));
    }
    for (int off = 16; off > 0; off >>= 1)
        m = fmaxf(m, __shfl_xor_sync(0xFFFFFFFF, m, off));

    float sum = 0.f;
#pragma unroll
    for (int i = 0; i < 16; i++) {
        float e = (vals[i] == -INFINITY) ? 0.f : __expf(vals[i] - m);
        vals[i] = e;
        sum += e;
    }
    for (int off = 16; off > 0; off >>= 1)
        sum += __shfl_xor_sync(0xFFFFFFFF, sum, off);

    float inv = (sum > 0.f) ? (1.f / sum) : 0.f;
#pragma unroll
    for (int i = 0; i < 4; i++) {
        float4 o = {vals[i * 4 + 0] * inv, vals[i * 4 + 1] * inv,
                    vals[i * 4 + 2] * inv, vals[i * 4 + 3] * inv};
        *(float4*)&probs[warp][i * 128 + lane * 4] = o;
    }
    __syncthreads();

    if (threadIdx.x < 128) {
        int s4 = threadIdx.x * 4;
        float4 a = {0.f, 0.f, 0.f, 0.f};
#pragma unroll
        for (int h = 0; h < 8; h++) {
            float4 p = *(const float4*)&probs[h][s4];
            a.x += p.x; a.y += p.y; a.z += p.z; a.w += p.w;
        }
        float4 o = {a.x * 0.125f, a.y * 0.125f, a.z * 0.125f, a.w * 0.125f};
        *(float4*)&g_attn[(size_t)bt * Sv + s4] = o;
    }
}

// ---------------- K5: dense output + sparse scatter (lse from g_lse) ----------------
__global__ __launch_bounds__(512)
void out_scatter_kernel(const float* __restrict__ logits,
                        const int* __restrict__ ids,
                        float* __restrict__ out) {
    int bt = blockIdx.x;
    int tid = threadIdx.x;
    int b = bt / Tv;
    const float4* row = (const float4*)(logits + (size_t)bt * Vv);
    __shared__ int sid[512];

    float lse = g_lse[bt];
    float l1m = g_log1mcp[bt];
    float lcp = g_logcp[bt];
    float p1c = LOG_EPS + lcp;                 // may be -inf
    float lnA = l1m - lse;                      // may be -inf
    float Cc  = __expf(p1c);                    // exp(-inf) = 0
    float tv  = (p1c > -1e30f) ? p1c : FMINF;

    sid[tid] = ids[b * Sv + tid];

    // dense write: out = log(exp(x + lnA) + C)
    float4* orow = (float4*)(out + (size_t)bt * VTv);
    for (int i = tid; i < VTv / 4; i += 512) {
        float4 o;
        if (i < Vv / 4) {
            float4 v = row[i];
            o.x = __logf(expp(v.x + lnA) + Cc);
            o.y = __logf(expp(v.y + lnA) + Cc);
            o.z = __logf(expp(v.z + lnA) + Cc);
            o.w = __logf(expp(v.w + lnA) + Cc);
        } else {
            o.x = o.y = o.z = o.w = tv;
        }
        orow[i] = o;
    }
    __syncthreads();

    // sparse scatter fix-up (full precision on touched slots)
    int c = g_canon[b * Sv + tid];
    if (c < 0) return;
    int id = sid[tid];

    float sum = g_attn[(size_t)bt * Sv + tid];
    if (c > 0) {
        for (int j = tid + 1; j < Sv; j++)
            if (sid[j] == id) sum += g_attn[(size_t)bt * Sv + j];
    }

    float p0;
    if (id < Vv) {
        p0 = fmaxf(logits[(size_t)bt * Vv + id] - lse + l1m, FMINF);
    } else {
        p0 = FMINF;
    }
    float plp = (sum > 0.f) ? logf(sum) : LOG_EPS;
    float p1 = plp + lcp;
    if (p1 == -INFINITY) p1 = FMINF;

    out[(size_t)bt * VTv + id] = lae(p0, p1);
}

// ---------------- launch ----------------
extern "C" void kernel_launch(void* const* d_in, const int* in_sizes, int n_in,
                              void* d_out, int out_size) {
    const float* logits = (const float*)d_in[0];
    const int*   ids    = (const int*)d_in[1];
    const float* src    = (const float*)d_in[2];
    const void*  pad    = d_in[3];
    const float* tgt    = (const float*)d_in[4];
    const float* w_q    = (const float*)d_in[5];
    const float* b_q    = (const float*)d_in[6];
    const float* w_k    = (const float*)d_in[7];
    const float* b_k    = (const float*)d_in[8];
    const float* w_copy = (const float*)d_in[9];
    const float* b_copy = (const float*)d_in[10];
    float* out = (float*)d_out;

    // persistent side stream + events (created once, before any capture)
    static cudaStream_t s2 = nullptr;
    static cudaEvent_t evFork = nullptr, evJoin = nullptr;
    if (s2 == nullptr) {
        cudaStreamCreateWithFlags(&s2, cudaStreamNonBlocking);
        cudaEventCreateWithFlags(&evFork, cudaEventDisableTiming);
        cudaEventCreateWithFlags(&evJoin, cudaEventDisableTiming);
        cudaFuncSetAttribute(gemm_mma_kernel,
                             cudaFuncAttributeMaxDynamicSharedMemorySize, GSM);
    }

    // fork: lse over logits runs concurrently with the projection/attention chain
    cudaEventRecord(evFork, 0);
    cudaStreamWaitEvent(s2, evFork, 0);
    lse_sum_kernel<<<Bv * Tv, 512, 0, s2>>>(logits);
    cudaEventRecord(evJoin, s2);

    prep_all_kernel<<<2184, 512>>>(pad, ids, tgt, w_copy, b_copy, src, w_k, w_q);
    gemm_mma_kernel<<<dim3(4, 36), 256, GSM>>>(b_k, b_q);
    scores_kernel<<<dim3(Bv * Hv, 4), 128>>>();
    softmax_mean_kernel<<<Bv * Tv, 256>>>();

    // join, then final output pass
    cudaStreamWaitEvent(0, evJoin, 0);
    out_scatter_kernel<<<Bv * Tv, 512>>>(logits, ids, out);
}

// round 8
// speedup vs baseline: 1.8987x; 1.8987x over previous
#include <cuda_runtime.h>
#include <cuda_bf16.h>
#include <math.h>
#include <stdint.h>

#define Bv 8
#define Sv 512
#define Tv 64
#define Dv 512
#define Hv 8
#define Vv 32000
#define EVv 2048
#define VTv 34048

#define FMINF (-3.402823466e38f)
#define LOG_EPS (-15.9423847198486328125f)   /* logf(2^-23) */

// ---------------- scratch ----------------
__device__ __align__(16) float g_k[Bv*Sv*Dv];         // 8 MB
__device__ __align__(16) float g_q[Bv*Tv*Dv];         // 1 MB
__device__ __align__(16) float g_scores[Bv*Hv*Tv*Sv]; // 8 MB
__device__ __align__(16) float g_attn[Bv*Tv*Sv];      // 1 MB
__device__ __align__(16) float g_maskf[Bv*Sv];        // 0 or -inf
__device__ float g_logcp[Bv*Tv];
__device__ float g_log1mcp[Bv*Tv];
__device__ float g_lse[Bv*Tv];
__device__ int   g_canon[Bv*Sv];

// bf16 split copies (activations stacked: rows 0..4095 = src, 4096..4607 = tgt)
__device__ __align__(16) __nv_bfloat16 g_a_hi[4608*512];
__device__ __align__(16) __nv_bfloat16 g_a_lo[4608*512];
// transposed weights: slice 0 = w_k^T [n][k], slice 1 = w_q^T
__device__ __align__(16) __nv_bfloat16 g_wt_hi[2*512*512];
__device__ __align__(16) __nv_bfloat16 g_wt_lo[2*512*512];

// ---------------- helpers ----------------
__device__ __forceinline__ float lae(float a, float b) {
    float m = fmaxf(a, b);
    return m + log1pf(__expf(-fabsf(a - b)));
}

// fast exp on the FMA pipe (poly 2^f; rel err ~5e-5)
__device__ __forceinline__ float expp(float x) {
    x = fmaxf(x, -80.0f);
    float y = x * 1.44269504f;
    float n = rintf(y);
    float f = y - n;
    float p = 0.00961813f;
    p = fmaf(p, f, 0.05550411f);
    p = fmaf(p, f, 0.24022651f);
    p = fmaf(p, f, 0.69314718f);
    p = fmaf(p, f, 1.0f);
    float s = __int_as_float(((int)n + 127) << 23);
    return p * s;
}

__device__ __forceinline__ uint32_t smem_u32(const void* p) {
    uint32_t a;
    asm("{ .reg .u64 t; cvta.to.shared.u64 t, %1; cvt.u32.u64 %0, t; }" : "=r"(a) : "l"(p));
    return a;
}
__device__ __forceinline__ void ldsm4(uint32_t* r, uint32_t addr) {
    asm volatile("ldmatrix.sync.aligned.m8n8.x4.shared.b16 {%0,%1,%2,%3}, [%4];"
                 : "=r"(r[0]), "=r"(r[1]), "=r"(r[2]), "=r"(r[3]) : "r"(addr));
}
__device__ __forceinline__ void mma_bf16(float* d, const uint32_t* a, const uint32_t* b) {
    asm volatile(
        "mma.sync.aligned.m16n8k16.row.col.f32.bf16.bf16.f32 "
        "{%0,%1,%2,%3}, {%4,%5,%6,%7}, {%8,%9}, {%0,%1,%2,%3};"
        : "+f"(d[0]), "+f"(d[1]), "+f"(d[2]), "+f"(d[3])
        : "r"(a[0]), "r"(a[1]), "r"(a[2]), "r"(a[3]), "r"(b[0]), "r"(b[1]));
}
__device__ __forceinline__ void cpa16(uint32_t s, const void* g) {
    asm volatile("cp.async.cg.shared.global [%0], [%1], 16;" :: "r"(s), "l"(g));
}

// ---------------- K1: prep_all = canon+mask / copygate / conv_a / conv_w ----------------
__global__ __launch_bounds__(512)
void prep_all_kernel(const void* __restrict__ pad,
                     const int* __restrict__ ids,
                     const float* __restrict__ tgt,
                     const float* __restrict__ wc,
                     const float* __restrict__ bc,
                     const float* __restrict__ src,
                     const float* __restrict__ wk,
                     const float* __restrict__ wq) {
    int bid = blockIdx.x;
    int tid = threadIdx.x;

    if (bid < 8) {
        // canonical representative + float mask for batch b
        int b = bid;
        __shared__ int sid[512];
        __shared__ int bad;
        if (tid == 0) bad = 0;
        sid[tid] = ids[b * Sv + tid];
        __syncthreads();
        // pad dtype sniff (first 4096 bytes — safe under bool or int layout)
        const unsigned* w = (const unsigned*)pad;
        for (int i = tid; i < 1024; i += 512)
            if (w[i] > 1u) atomicOr(&bad, 1);
        int my = sid[tid];
        bool canon = true;
        for (int j = 0; j < tid; j++)
            if (sid[j] == my) { canon = false; break; }
        int cnt = 0;
        if (canon)
            for (int j = tid + 1; j < Sv; j++) cnt += (sid[j] == my);
        g_canon[b * Sv + tid] = canon ? cnt : -1;
        __syncthreads();
        bool isint = (bad == 0);
        int idx = b * Sv + tid;
        bool p = isint ? (((const int*)pad)[idx] != 0)
                       : (((const unsigned char*)pad)[idx] != 0);
        g_maskf[idx] = p ? -INFINITY : 0.0f;
        return;
    }
    if (bid < 520) {
        // copy gate
        int bt = bid - 8;
        float acc = tgt[(size_t)bt * Dv + tid] * wc[tid];
        for (int off = 16; off > 0; off >>= 1)
            acc += __shfl_xor_sync(0xFFFFFFFF, acc, off);
        __shared__ float sred[16];
        int warp = tid >> 5, lane = tid & 31;
        if (lane == 0) sred[warp] = acc;
        __syncthreads();
        if (tid == 0) {
            float z = bc[0];
            for (int i = 0; i < 16; i++) z += sred[i];
            float cp = 1.f / (1.f + expf(-z));
            g_logcp[bt]   = logf(cp);
            g_log1mcp[bt] = logf(1.f - cp);
        }
        return;
    }
    if (bid < 1672) {
        // convert activations: fp32 -> bf16 hi/lo
        int q = (bid - 520) * 512 + tid;
        int row = q >> 7;
        int c4  = (q & 127) * 4;
        float4 v = (row < 4096)
            ? *(const float4*)&src[(size_t)row * 512 + c4]
            : *(const float4*)&tgt[(size_t)(row - 4096) * 512 + c4];
        float xs[4] = {v.x, v.y, v.z, v.w};
        unsigned short h[4], l[4];
#pragma unroll
        for (int i = 0; i < 4; i++) {
            __nv_bfloat16 hb = __float2bfloat16(xs[i]);
            float lo = xs[i] - __bfloat162float(hb);
            h[i] = __bfloat16_as_ushort(hb);
            l[i] = __bfloat16_as_ushort(__float2bfloat16(lo));
        }
        uint2 H = {(unsigned)h[0] | ((unsigned)h[1] << 16), (unsigned)h[2] | ((unsigned)h[3] << 16)};
        uint2 L = {(unsigned)l[0] | ((unsigned)l[1] << 16), (unsigned)l[2] | ((unsigned)l[3] << 16)};
        *(uint2*)&g_a_hi[(size_t)row * 512 + c4] = H;
        *(uint2*)&g_a_lo[(size_t)row * 512 + c4] = L;
        return;
    }
    // transpose + convert weights
    {
        int bid2 = bid - 1672;
        int z = bid2 >> 8;
        const float* W = z ? wq : wk;
        int r = bid2 & 255;
        int n0 = (r & 15) * 32, k0 = (r >> 4) * 32;
        __shared__ float tile[32][33];
        int tx = tid & 31, ty = tid >> 5;
#pragma unroll
        for (int i = 0; i < 2; i++)
            tile[ty + i * 16][tx] = W[(size_t)(k0 + ty + i * 16) * 512 + n0 + tx];
        __syncthreads();
#pragma unroll
        for (int i = 0; i < 2; i++) {
            int n = n0 + ty + i * 16;
            int k = k0 + tx;
            float x = tile[tx][ty + i * 16];
            __nv_bfloat16 hb = __float2bfloat16(x);
            float lo = x - __bfloat162float(hb);
            size_t o = (size_t)z * 262144 + (size_t)n * 512 + k;
            g_wt_hi[o] = hb;
            g_wt_lo[o] = __float2bfloat16(lo);
        }
    }
}

// ---------------- K-lse: S = sum exp(logits row); lse -> g_lse ----------------
__global__ __launch_bounds__(512)
void lse_sum_kernel(const float* __restrict__ logits) {
    int bt = blockIdx.x;
    int tid = threadIdx.x;
    const float4* row = (const float4*)(logits + (size_t)bt * Vv);
    __shared__ float ssum[16];
    int warp = tid >> 5, lane = tid & 31;

    float s = 0.f;
    for (int i = tid; i < Vv / 4; i += 512) {
        float4 v = row[i];
        s += expp(v.x) + expp(v.y) + expp(v.z) + expp(v.w);
    }
    for (int off = 16; off > 0; off >>= 1)
        s += __shfl_xor_sync(0xFFFFFFFF, s, off);
    if (lane == 0) ssum[warp] = s;
    __syncthreads();
    if (tid == 0) {
        float S = ssum[0];
#pragma unroll
        for (int i = 1; i < 16; i++) S += ssum[i];
        g_lse[bt] = __logf(S);
    }
}

// ---------------- K2: HMMA dual GEMM, BM=128 BN=128, 3-stage cp.async, K_CHUNK=32 ----------------
#define A_HI 0
#define A_LO 10240
#define B_HI 20480
#define B_LO 30720
#define STG_SZ 40960
#define GSM (3 * STG_SZ)

__global__ __launch_bounds__(256)
void gemm_mma_kernel(const float* __restrict__ b_k, const float* __restrict__ b_q) {
    extern __shared__ __align__(16) char sm[];
    int tid = threadIdx.x;
    int lane = tid & 31;
    int wid = tid >> 5;
    int wm = wid & 1, wn = wid >> 1;   // 2m x 4n, warp tile 64x32

    int yb = blockIdx.y;
    bool isQ = (yb >= 32);
    int arow0 = isQ ? 4096 + (yb - 32) * 128 : yb * 128;
    int orow0 = isQ ? (yb - 32) * 128 : yb * 128;
    float* C = isQ ? g_q : g_k;
    const float* bias = isQ ? b_q : b_k;
    int n0 = blockIdx.x * 128;
    size_t wtb = (isQ ? (size_t)262144 : 0) + (size_t)n0 * 512;

    uint32_t sbase = smem_u32(sm);

    auto issue_chunk = [&](int kc, int st) {
        uint32_t sb = sbase + st * STG_SZ;
#pragma unroll
        for (int i = 0; i < 2; i++) {
            int idx = tid + i * 256;
            int r = idx >> 2, c = idx & 3;
            uint32_t d = (uint32_t)(r * 80 + c * 16);
            size_t ga = (size_t)(arow0 + r) * 512 + kc * 32 + c * 8;
            cpa16(sb + A_HI + d, &g_a_hi[ga]);
            cpa16(sb + A_LO + d, &g_a_lo[ga]);
            size_t gb = wtb + (size_t)r * 512 + kc * 32 + c * 8;
            cpa16(sb + B_HI + d, &g_wt_hi[gb]);
            cpa16(sb + B_LO + d, &g_wt_lo[gb]);
        }
        asm volatile("cp.async.commit_group;" ::: "memory");
    };

    int a_row = (lane & 7) + ((lane >> 3) & 1) * 8;
    int a_k8  = (lane >> 4) * 8;
    int b_row = (lane & 7) + (lane >> 4) * 8;
    int b_k8  = ((lane >> 3) & 1) * 8;

    float acc[4][4][4] = {};

    issue_chunk(0, 0);
    issue_chunk(1, 1);

#pragma unroll 1
    for (int kc = 0; kc < 16; kc++) {
        if (kc < 14) asm volatile("cp.async.wait_group 1;" ::: "memory");
        else         asm volatile("cp.async.wait_group 0;" ::: "memory");
        __syncthreads();
        if (kc + 2 < 16) issue_chunk(kc + 2, (kc + 2) % 3);

        uint32_t cb = sbase + (uint32_t)((kc % 3) * STG_SZ);
        uint32_t aB = cb + A_HI + (uint32_t)(wm * 64 + a_row) * 80 + a_k8 * 2;
        uint32_t bB = cb + B_HI + (uint32_t)(wn * 32 + b_row) * 80 + b_k8 * 2;

#pragma unroll
        for (int ks = 0; ks < 2; ks++) {
            uint32_t bh0[4], bh1[4], bl0[4], bl1[4];
            uint32_t ba = bB + ks * 32;
            ldsm4(bh0, ba);
            ldsm4(bh1, ba + 16 * 80);
            ldsm4(bl0, ba + (B_LO - B_HI));
            ldsm4(bl1, ba + (B_LO - B_HI) + 16 * 80);
#pragma unroll
            for (int mt = 0; mt < 4; mt++) {
                uint32_t ah[4], al[4];
                uint32_t aa = aB + (uint32_t)(mt * 16) * 80 + ks * 32;
                ldsm4(ah, aa);
                ldsm4(al, aa + (A_LO - A_HI));
                mma_bf16(acc[mt][0], ah, bh0);
                mma_bf16(acc[mt][0], ah, bl0);
                mma_bf16(acc[mt][0], al, bh0);
                mma_bf16(acc[mt][1], ah, bh0 + 2);
                mma_bf16(acc[mt][1], ah, bl0 + 2);
                mma_bf16(acc[mt][1], al, bh0 + 2);
                mma_bf16(acc[mt][2], ah, bh1);
                mma_bf16(acc[mt][2], ah, bl1);
                mma_bf16(acc[mt][2], al, bh1);
                mma_bf16(acc[mt][3], ah, bh1 + 2);
                mma_bf16(acc[mt][3], ah, bl1 + 2);
                mma_bf16(acc[mt][3], al, bh1 + 2);
            }
        }
    }

    // epilogue
    int g = lane >> 2, t4 = lane & 3;
#pragma unroll
    for (int mt = 0; mt < 4; mt++) {
#pragma unroll
        for (int nt = 0; nt < 4; nt++) {
            int col = n0 + wn * 32 + nt * 8 + t4 * 2;
            float2 bb = *(const float2*)&bias[col];
            int row0 = orow0 + wm * 64 + mt * 16 + g;
            float2 v0 = {acc[mt][nt][0] + bb.x, acc[mt][nt][1] + bb.y};
            float2 v1 = {acc[mt][nt][2] + bb.x, acc[mt][nt][3] + bb.y};
            *(float2*)&C[(size_t)row0 * 512 + col] = v0;
            *(float2*)&C[(size_t)(row0 + 8) * 512 + col] = v1;
        }
    }
}

// ---------------- K3: scores v3 — 256 threads, micro 8t x 4s ----------------
__global__ __launch_bounds__(256)
void scores_kernel() {
    __shared__ __align__(16) float kT[64][128];  // [d][s]
    __shared__ __align__(16) float qT[64][72];   // [d][t], padded
    int bh = blockIdx.x;
    int b = bh >> 3, h = bh & 7;
    int s0 = blockIdx.y * 128;
    int tid = threadIdx.x;

    // load K chunk transposed: 2 threads per s (each 32 d)
    {
        int s = tid & 127, half = tid >> 7;
        const float* kp = &g_k[((size_t)(b * Sv + s0 + s)) * Dv + h * 64 + half * 32];
#pragma unroll
        for (int j = 0; j < 8; j++) {
            float4 v = *(const float4*)&kp[j * 4];
            int d = half * 32 + j * 4;
            kT[d + 0][s] = v.x;
            kT[d + 1][s] = v.y;
            kT[d + 2][s] = v.z;
            kT[d + 3][s] = v.w;
        }
    }
    // load Q transposed: 4 threads per t (each 16 d)
    {
        int t = tid & 63, dh = tid >> 6;
        const float* qp = &g_q[((size_t)(b * Tv + t)) * Dv + h * 64 + dh * 16];
#pragma unroll
        for (int j = 0; j < 4; j++) {
            float4 v = *(const float4*)&qp[j * 4];
            int d = dh * 16 + j * 4;
            qT[d + 0][t] = v.x;
            qT[d + 1][t] = v.y;
            qT[d + 2][t] = v.z;
            qT[d + 3][t] = v.w;
        }
    }
    __syncthreads();

    int tx = tid & 31, ty = tid >> 5;   // 32 s-groups (4 s) x 8 t-groups (8 t)
    float acc[8][4] = {};
#pragma unroll
    for (int kk = 0; kk < 64; kk++) {
        float4 a0 = *(const float4*)&qT[kk][ty * 8];
        float4 a1 = *(const float4*)&qT[kk][ty * 8 + 4];
        float4 b0 = *(const float4*)&kT[kk][tx * 4];
        float av[8] = {a0.x, a0.y, a0.z, a0.w, a1.x, a1.y, a1.z, a1.w};
        float bv[4] = {b0.x, b0.y, b0.z, b0.w};
#pragma unroll
        for (int i = 0; i < 8; i++)
#pragma unroll
            for (int j = 0; j < 4; j++)
                acc[i][j] += av[i] * bv[j];
    }

    float* op = &g_scores[(((size_t)(b * Hv + h)) * Tv) * Sv + s0];
#pragma unroll
    for (int i = 0; i < 8; i++) {
        int t = ty * 8 + i;
        float4 o = {acc[i][0] * 0.125f, acc[i][1] * 0.125f,
                    acc[i][2] * 0.125f, acc[i][3] * 0.125f};
        *(float4*)&op[(size_t)t * Sv + tx * 4] = o;
    }
}

// ---------------- K4: masked softmax per head + mean over heads (float4) ----------------
__global__ __launch_bounds__(256)
void softmax_mean_kernel() {
    int bt = blockIdx.x;
    int b = bt / Tv, t = bt % Tv;
    int warp = threadIdx.x >> 5, lane = threadIdx.x & 31;

    __shared__ float probs[8][512];

    const float* sc = &g_scores[(((size_t)b * Hv + warp) * Tv + t) * Sv];
    const float* mk = &g_maskf[b * Sv];

    float vals[16];
    float m = -INFINITY;
#pragma unroll
    for (int i = 0; i < 4; i++) {
        int s = i * 128 + lane * 4;
        float4 v = *(const float4*)&sc[s];
        float4 q = *(const float4*)&mk[s];
        v.x += q.x; v.y += q.y; v.z += q.z; v.w += q.w;
        vals[i * 4 + 0] = v.x; vals[i * 4 + 1] = v.y;
        vals[i * 4 + 2] = v.z; vals[i * 4 + 3] = v.w;
        m = fmaxf(m, fmaxf(fmaxf(v.x, v.y), fmaxf(v.z, v.w)));
    }
    for (int off = 16; off > 0; off >>= 1)
        m = fmaxf(m, __shfl_xor_sync(0xFFFFFFFF, m, off));

    float sum = 0.f;
#pragma unroll
    for (int i = 0; i < 16; i++) {
        float e = (vals[i] == -INFINITY) ? 0.f : __expf(vals[i] - m);
        vals[i] = e;
        sum += e;
    }
    for (int off = 16; off > 0; off >>= 1)
        sum += __shfl_xor_sync(0xFFFFFFFF, sum, off);

    float inv = (sum > 0.f) ? (1.f / sum) : 0.f;
#pragma unroll
    for (int i = 0; i < 4; i++) {
        float4 o = {vals[i * 4 + 0] * inv, vals[i * 4 + 1] * inv,
                    vals[i * 4 + 2] * inv, vals[i * 4 + 3] * inv};
        *(float4*)&probs[warp][i * 128 + lane * 4] = o;
    }
    __syncthreads();

    if (threadIdx.x < 128) {
        int s4 = threadIdx.x * 4;
        float4 a = {0.f, 0.f, 0.f, 0.f};
#pragma unroll
        for (int h = 0; h < 8; h++) {
            float4 p = *(const float4*)&probs[h][s4];
            a.x += p.x; a.y += p.y; a.z += p.z; a.w += p.w;
        }
        float4 o = {a.x * 0.125f, a.y * 0.125f, a.z * 0.125f, a.w * 0.125f};
        *(float4*)&g_attn[(size_t)bt * Sv + s4] = o;
    }
}

// ---------------- K5: dense output + sparse scatter (lse from g_lse) ----------------
__global__ __launch_bounds__(512)
void out_scatter_kernel(const float* __restrict__ logits,
                        const int* __restrict__ ids,
                        float* __restrict__ out) {
    int bt = blockIdx.x;
    int tid = threadIdx.x;
    int b = bt / Tv;
    const float4* row = (const float4*)(logits + (size_t)bt * Vv);
    __shared__ int sid[512];

    float lse = g_lse[bt];
    float l1m = g_log1mcp[bt];
    float lcp = g_logcp[bt];
    float p1c = LOG_EPS + lcp;
    float lnA = l1m - lse;
    float Cc  = __expf(p1c);
    float tv  = (p1c > -1e30f) ? p1c : FMINF;

    sid[tid] = ids[b * Sv + tid];

    float4* orow = (float4*)(out + (size_t)bt * VTv);
    for (int i = tid; i < VTv / 4; i += 512) {
        float4 o;
        if (i < Vv / 4) {
            float4 v = row[i];
            o.x = __logf(expp(v.x + lnA) + Cc);
            o.y = __logf(expp(v.y + lnA) + Cc);
            o.z = __logf(expp(v.z + lnA) + Cc);
            o.w = __logf(expp(v.w + lnA) + Cc);
        } else {
            o.x = o.y = o.z = o.w = tv;
        }
        orow[i] = o;
    }
    __syncthreads();

    int c = g_canon[b * Sv + tid];
    if (c < 0) return;
    int id = sid[tid];

    float sum = g_attn[(size_t)bt * Sv + tid];
    if (c > 0) {
        for (int j = tid + 1; j < Sv; j++)
            if (sid[j] == id) sum += g_attn[(size_t)bt * Sv + j];
    }

    float p0;
    if (id < Vv) {
        p0 = fmaxf(logits[(size_t)bt * Vv + id] - lse + l1m, FMINF);
    } else {
        p0 = FMINF;
    }
    float plp = (sum > 0.f) ? logf(sum) : LOG_EPS;
    float p1 = plp + lcp;
    if (p1 == -INFINITY) p1 = FMINF;

    out[(size_t)bt * VTv + id] = lae(p0, p1);
}

// ---------------- launch (single stream — no fork; capture-safe) ----------------
extern "C" void kernel_launch(void* const* d_in, const int* in_sizes, int n_in,
                              void* d_out, int out_size) {
    const float* logits = (const float*)d_in[0];
    const int*   ids    = (const int*)d_in[1];
    const float* src    = (const float*)d_in[2];
    const void*  pad    = d_in[3];
    const float* tgt    = (const float*)d_in[4];
    const float* w_q    = (const float*)d_in[5];
    const float* b_q    = (const float*)d_in[6];
    const float* w_k    = (const float*)d_in[7];
    const float* b_k    = (const float*)d_in[8];
    const float* w_copy = (const float*)d_in[9];
    const float* b_copy = (const float*)d_in[10];
    float* out = (float*)d_out;

    cudaFuncSetAttribute(gemm_mma_kernel,
                         cudaFuncAttributeMaxDynamicSharedMemorySize, GSM);

    prep_all_kernel<<<2184, 512>>>(pad, ids, tgt, w_copy, b_copy, src, w_k, w_q);
    gemm_mma_kernel<<<dim3(4, 36), 256, GSM>>>(b_k, b_q);
    scores_kernel<<<dim3(Bv * Hv, 4), 256>>>();
    softmax_mean_kernel<<<Bv * Tv, 256>>>();
    lse_sum_kernel<<<Bv * Tv, 512>>>(logits);
    out_scatter_kernel<<<Bv * Tv, 512>>>(logits, ids, out);
}

// round 9
// speedup vs baseline: 1.9871x; 1.0466x over previous
#include <cuda_runtime.h>
#include <cuda_bf16.h>
#include <math.h>
#include <stdint.h>

#define Bv 8
#define Sv 512
#define Tv 64
#define Dv 512
#define Hv 8
#define Vv 32000
#define EVv 2048
#define VTv 34048

#define FMINF (-3.402823466e38f)
#define LOG_EPS (-15.9423847198486328125f)   /* logf(2^-23) */

// ---------------- scratch ----------------
__device__ __align__(16) float g_k[Bv*Sv*Dv];         // 8 MB
__device__ __align__(16) float g_q[Bv*Tv*Dv];         // 1 MB
__device__ __align__(16) float g_scores[Bv*Hv*Tv*Sv]; // 8 MB
__device__ __align__(16) float g_attn[Bv*Tv*Sv];      // 1 MB
__device__ __align__(16) float g_maskf[Bv*Sv];        // 0 or -inf
__device__ float g_logcp[Bv*Tv];
__device__ float g_log1mcp[Bv*Tv];
__device__ int   g_canon[Bv*Sv];

// bf16 split copies (activations stacked: rows 0..4095 = src, 4096..4607 = tgt)
__device__ __align__(16) __nv_bfloat16 g_a_hi[4608*512];
__device__ __align__(16) __nv_bfloat16 g_a_lo[4608*512];
// transposed weights: slice 0 = w_k^T [n][k], slice 1 = w_q^T
__device__ __align__(16) __nv_bfloat16 g_wt_hi[2*512*512];
__device__ __align__(16) __nv_bfloat16 g_wt_lo[2*512*512];

// ---------------- helpers ----------------
__device__ __forceinline__ float lae(float a, float b) {
    float m = fmaxf(a, b);
    return m + log1pf(__expf(-fabsf(a - b)));
}

// fast exp on the FMA pipe (poly 2^f; rel err ~5e-5)
__device__ __forceinline__ float expp(float x) {
    x = fmaxf(x, -80.0f);
    float y = x * 1.44269504f;
    float n = rintf(y);
    float f = y - n;
    float p = 0.00961813f;
    p = fmaf(p, f, 0.05550411f);
    p = fmaf(p, f, 0.24022651f);
    p = fmaf(p, f, 0.69314718f);
    p = fmaf(p, f, 1.0f);
    float s = __int_as_float(((int)n + 127) << 23);
    return p * s;
}

__device__ __forceinline__ uint32_t smem_u32(const void* p) {
    uint32_t a;
    asm("{ .reg .u64 t; cvta.to.shared.u64 t, %1; cvt.u32.u64 %0, t; }" : "=r"(a) : "l"(p));
    return a;
}
__device__ __forceinline__ void ldsm4(uint32_t* r, uint32_t addr) {
    asm volatile("ldmatrix.sync.aligned.m8n8.x4.shared.b16 {%0,%1,%2,%3}, [%4];"
                 : "=r"(r[0]), "=r"(r[1]), "=r"(r[2]), "=r"(r[3]) : "r"(addr));
}
__device__ __forceinline__ void mma_bf16(float* d, const uint32_t* a, const uint32_t* b) {
    asm volatile(
        "mma.sync.aligned.m16n8k16.row.col.f32.bf16.bf16.f32 "
        "{%0,%1,%2,%3}, {%4,%5,%6,%7}, {%8,%9}, {%0,%1,%2,%3};"
        : "+f"(d[0]), "+f"(d[1]), "+f"(d[2]), "+f"(d[3])
        : "r"(a[0]), "r"(a[1]), "r"(a[2]), "r"(a[3]), "r"(b[0]), "r"(b[1]));
}
__device__ __forceinline__ void cpa16(uint32_t s, const void* g) {
    asm volatile("cp.async.cg.shared.global [%0], [%1], 16;" :: "r"(s), "l"(g));
}

// ---------------- K1: prep_all = canon+mask / copygate / conv_a / conv_w ----------------
__global__ __launch_bounds__(512)
void prep_all_kernel(const void* __restrict__ pad,
                     const int* __restrict__ ids,
                     const float* __restrict__ tgt,
                     const float* __restrict__ wc,
                     const float* __restrict__ bc,
                     const float* __restrict__ src,
                     const float* __restrict__ wk,
                     const float* __restrict__ wq) {
    int bid = blockIdx.x;
    int tid = threadIdx.x;

    if (bid < 8) {
        // canonical representative + float mask for batch b
        int b = bid;
        __shared__ int sid[512];
        __shared__ int bad;
        if (tid == 0) bad = 0;
        sid[tid] = ids[b * Sv + tid];
        __syncthreads();
        // pad dtype sniff (first 4096 bytes — safe under bool or int layout)
        const unsigned* w = (const unsigned*)pad;
        for (int i = tid; i < 1024; i += 512)
            if (w[i] > 1u) atomicOr(&bad, 1);
        int my = sid[tid];
        bool canon = true;
        for (int j = 0; j < tid; j++)
            if (sid[j] == my) { canon = false; break; }
        int cnt = 0;
        if (canon)
            for (int j = tid + 1; j < Sv; j++) cnt += (sid[j] == my);
        g_canon[b * Sv + tid] = canon ? cnt : -1;
        __syncthreads();
        bool isint = (bad == 0);
        int idx = b * Sv + tid;
        bool p = isint ? (((const int*)pad)[idx] != 0)
                       : (((const unsigned char*)pad)[idx] != 0);
        g_maskf[idx] = p ? -INFINITY : 0.0f;
        return;
    }
    if (bid < 520) {
        // copy gate
        int bt = bid - 8;
        float acc = tgt[(size_t)bt * Dv + tid] * wc[tid];
        for (int off = 16; off > 0; off >>= 1)
            acc += __shfl_xor_sync(0xFFFFFFFF, acc, off);
        __shared__ float sred[16];
        int warp = tid >> 5, lane = tid & 31;
        if (lane == 0) sred[warp] = acc;
        __syncthreads();
        if (tid == 0) {
            float z = bc[0];
            for (int i = 0; i < 16; i++) z += sred[i];
            float cp = 1.f / (1.f + expf(-z));
            g_logcp[bt]   = logf(cp);
            g_log1mcp[bt] = logf(1.f - cp);
        }
        return;
    }
    if (bid < 1672) {
        // convert activations: fp32 -> bf16 hi/lo
        int q = (bid - 520) * 512 + tid;
        int row = q >> 7;
        int c4  = (q & 127) * 4;
        float4 v = (row < 4096)
            ? *(const float4*)&src[(size_t)row * 512 + c4]
            : *(const float4*)&tgt[(size_t)(row - 4096) * 512 + c4];
        float xs[4] = {v.x, v.y, v.z, v.w};
        unsigned short h[4], l[4];
#pragma unroll
        for (int i = 0; i < 4; i++) {
            __nv_bfloat16 hb = __float2bfloat16(xs[i]);
            float lo = xs[i] - __bfloat162float(hb);
            h[i] = __bfloat16_as_ushort(hb);
            l[i] = __bfloat16_as_ushort(__float2bfloat16(lo));
        }
        uint2 H = {(unsigned)h[0] | ((unsigned)h[1] << 16), (unsigned)h[2] | ((unsigned)h[3] << 16)};
        uint2 L = {(unsigned)l[0] | ((unsigned)l[1] << 16), (unsigned)l[2] | ((unsigned)l[3] << 16)};
        *(uint2*)&g_a_hi[(size_t)row * 512 + c4] = H;
        *(uint2*)&g_a_lo[(size_t)row * 512 + c4] = L;
        return;
    }
    // transpose + convert weights
    {
        int bid2 = bid - 1672;
        int z = bid2 >> 8;
        const float* W = z ? wq : wk;
        int r = bid2 & 255;
        int n0 = (r & 15) * 32, k0 = (r >> 4) * 32;
        __shared__ float tile[32][33];
        int tx = tid & 31, ty = tid >> 5;
#pragma unroll
        for (int i = 0; i < 2; i++)
            tile[ty + i * 16][tx] = W[(size_t)(k0 + ty + i * 16) * 512 + n0 + tx];
        __syncthreads();
#pragma unroll
        for (int i = 0; i < 2; i++) {
            int n = n0 + ty + i * 16;
            int k = k0 + tx;
            float x = tile[tx][ty + i * 16];
            __nv_bfloat16 hb = __float2bfloat16(x);
            float lo = x - __bfloat162float(hb);
            size_t o = (size_t)z * 262144 + (size_t)n * 512 + k;
            g_wt_hi[o] = hb;
            g_wt_lo[o] = __float2bfloat16(lo);
        }
    }
}

// ---------------- K2: HMMA dual GEMM — R6 config (BM=128 BN=64, 3-stage, K_CHUNK=32) ----------------
#define STG_A_LO 10240
#define STG_B_HI 20480
#define STG_B_LO 25600
#define STG_SZ   30720
#define GSM (3 * STG_SZ)

__global__ __launch_bounds__(256)
void gemm_mma_kernel(const float* __restrict__ b_k, const float* __restrict__ b_q) {
    extern __shared__ __align__(16) char sm[];
    int tid = threadIdx.x;
    int lane = tid & 31;
    int wid = tid >> 5;
    int wm = wid & 3, wn = wid >> 2;   // 4m x 2n, warp tile 32x32

    int yb = blockIdx.y;
    bool isQ = (yb >= 32);
    int arow0 = isQ ? 4096 + (yb - 32) * 128 : yb * 128;
    int orow0 = isQ ? (yb - 32) * 128 : yb * 128;
    float* C = isQ ? g_q : g_k;
    const float* bias = isQ ? b_q : b_k;
    int n0 = blockIdx.x * 64;
    size_t wtb = (isQ ? (size_t)262144 : 0) + (size_t)n0 * 512;

    uint32_t sbase = smem_u32(sm);

    auto issue_chunk = [&](int kc, int st) {
        uint32_t sb = sbase + st * STG_SZ;
#pragma unroll
        for (int i = 0; i < 2; i++) {
            int idx = tid + i * 256;
            int r = idx >> 2, c = idx & 3;
            size_t gg = (size_t)(arow0 + r) * 512 + kc * 32 + c * 8;
            uint32_t d = (uint32_t)(r * 80 + c * 16);
            cpa16(sb + d, &g_a_hi[gg]);
            cpa16(sb + STG_A_LO + d, &g_a_lo[gg]);
        }
        {
            int r = tid >> 2, c = tid & 3;
            size_t gg = wtb + (size_t)r * 512 + kc * 32 + c * 8;
            uint32_t d = (uint32_t)(r * 80 + c * 16);
            cpa16(sb + STG_B_HI + d, &g_wt_hi[gg]);
            cpa16(sb + STG_B_LO + d, &g_wt_lo[gg]);
        }
        asm volatile("cp.async.commit_group;" ::: "memory");
    };

    int a_row = (lane & 7) + ((lane >> 3) & 1) * 8;
    int a_k8  = (lane >> 4) * 8;
    int b_row = (lane & 7) + (lane >> 4) * 8;
    int b_k8  = ((lane >> 3) & 1) * 8;

    float acc[2][4][4] = {};

    issue_chunk(0, 0);
    issue_chunk(1, 1);

#pragma unroll 1
    for (int kc = 0; kc < 16; kc++) {
        if (kc < 14) asm volatile("cp.async.wait_group 1;" ::: "memory");
        else         asm volatile("cp.async.wait_group 0;" ::: "memory");
        __syncthreads();
        if (kc + 2 < 16) issue_chunk(kc + 2, (kc + 2) % 3);

        uint32_t cb = sbase + (uint32_t)((kc % 3) * STG_SZ);
        uint32_t aB = cb + (uint32_t)(wm * 32 + a_row) * 80 + a_k8 * 2;
        uint32_t bB = cb + STG_B_HI + (uint32_t)(wn * 32 + b_row) * 80 + b_k8 * 2;

#pragma unroll
        for (int ks = 0; ks < 2; ks++) {
            uint32_t bh0[4], bh1[4], bl0[4], bl1[4];
            uint32_t ba = bB + ks * 32;
            ldsm4(bh0, ba);
            ldsm4(bh1, ba + 16 * 80);
            ldsm4(bl0, ba + (STG_B_LO - STG_B_HI));
            ldsm4(bl1, ba + (STG_B_LO - STG_B_HI) + 16 * 80);
#pragma unroll
            for (int mt = 0; mt < 2; mt++) {
                uint32_t ah[4], al[4];
                uint32_t aa = aB + (uint32_t)(mt * 16) * 80 + ks * 32;
                ldsm4(ah, aa);
                ldsm4(al, aa + STG_A_LO);
                mma_bf16(acc[mt][0], ah, bh0);
                mma_bf16(acc[mt][0], ah, bl0);
                mma_bf16(acc[mt][0], al, bh0);
                mma_bf16(acc[mt][1], ah, bh0 + 2);
                mma_bf16(acc[mt][1], ah, bl0 + 2);
                mma_bf16(acc[mt][1], al, bh0 + 2);
                mma_bf16(acc[mt][2], ah, bh1);
                mma_bf16(acc[mt][2], ah, bl1);
                mma_bf16(acc[mt][2], al, bh1);
                mma_bf16(acc[mt][3], ah, bh1 + 2);
                mma_bf16(acc[mt][3], ah, bl1 + 2);
                mma_bf16(acc[mt][3], al, bh1 + 2);
            }
        }
    }

    // epilogue
    int g = lane >> 2, t4 = lane & 3;
#pragma unroll
    for (int mt = 0; mt < 2; mt++) {
#pragma unroll
        for (int nt = 0; nt < 4; nt++) {
            int col = n0 + wn * 32 + nt * 8 + t4 * 2;
            float2 bb = *(const float2*)&bias[col];
            int row0 = orow0 + wm * 32 + mt * 16 + g;
            float2 v0 = {acc[mt][nt][0] + bb.x, acc[mt][nt][1] + bb.y};
            float2 v1 = {acc[mt][nt][2] + bb.x, acc[mt][nt][3] + bb.y};
            *(float2*)&C[(size_t)row0 * 512 + col] = v0;
            *(float2*)&C[(size_t)(row0 + 8) * 512 + col] = v1;
        }
    }
}

// ---------------- K3: scores v3 — 256 threads, micro 8t x 4s ----------------
__global__ __launch_bounds__(256)
void scores_kernel() {
    __shared__ __align__(16) float kT[64][128];  // [d][s]
    __shared__ __align__(16) float qT[64][72];   // [d][t], padded
    int bh = blockIdx.x;
    int b = bh >> 3, h = bh & 7;
    int s0 = blockIdx.y * 128;
    int tid = threadIdx.x;

    {
        int s = tid & 127, half = tid >> 7;
        const float* kp = &g_k[((size_t)(b * Sv + s0 + s)) * Dv + h * 64 + half * 32];
#pragma unroll
        for (int j = 0; j < 8; j++) {
            float4 v = *(const float4*)&kp[j * 4];
            int d = half * 32 + j * 4;
            kT[d + 0][s] = v.x;
            kT[d + 1][s] = v.y;
            kT[d + 2][s] = v.z;
            kT[d + 3][s] = v.w;
        }
    }
    {
        int t = tid & 63, dh = tid >> 6;
        const float* qp = &g_q[((size_t)(b * Tv + t)) * Dv + h * 64 + dh * 16];
#pragma unroll
        for (int j = 0; j < 4; j++) {
            float4 v = *(const float4*)&qp[j * 4];
            int d = dh * 16 + j * 4;
            qT[d + 0][t] = v.x;
            qT[d + 1][t] = v.y;
            qT[d + 2][t] = v.z;
            qT[d + 3][t] = v.w;
        }
    }
    __syncthreads();

    int tx = tid & 31, ty = tid >> 5;
    float acc[8][4] = {};
#pragma unroll
    for (int kk = 0; kk < 64; kk++) {
        float4 a0 = *(const float4*)&qT[kk][ty * 8];
        float4 a1 = *(const float4*)&qT[kk][ty * 8 + 4];
        float4 b0 = *(const float4*)&kT[kk][tx * 4];
        float av[8] = {a0.x, a0.y, a0.z, a0.w, a1.x, a1.y, a1.z, a1.w};
        float bv[4] = {b0.x, b0.y, b0.z, b0.w};
#pragma unroll
        for (int i = 0; i < 8; i++)
#pragma unroll
            for (int j = 0; j < 4; j++)
                acc[i][j] += av[i] * bv[j];
    }

    float* op = &g_scores[(((size_t)(b * Hv + h)) * Tv) * Sv + s0];
#pragma unroll
    for (int i = 0; i < 8; i++) {
        int t = ty * 8 + i;
        float4 o = {acc[i][0] * 0.125f, acc[i][1] * 0.125f,
                    acc[i][2] * 0.125f, acc[i][3] * 0.125f};
        *(float4*)&op[(size_t)t * Sv + tx * 4] = o;
    }
}

// ---------------- K4: masked softmax per head + mean over heads (float4) ----------------
__global__ __launch_bounds__(256)
void softmax_mean_kernel() {
    int bt = blockIdx.x;
    int b = bt / Tv, t = bt % Tv;
    int warp = threadIdx.x >> 5, lane = threadIdx.x & 31;

    __shared__ float probs[8][512];

    const float* sc = &g_scores[(((size_t)b * Hv + warp) * Tv + t) * Sv];
    const float* mk = &g_maskf[b * Sv];

    float vals[16];
    float m = -INFINITY;
#pragma unroll
    for (int i = 0; i < 4; i++) {
        int s = i * 128 + lane * 4;
        float4 v = *(const float4*)&sc[s];
        float4 q = *(const float4*)&mk[s];
        v.x += q.x; v.y += q.y; v.z += q.z; v.w += q.w;
        vals[i * 4 + 0] = v.x; vals[i * 4 + 1] = v.y;
        vals[i * 4 + 2] = v.z; vals[i * 4 + 3] = v.w;
        m = fmaxf(m, fmaxf(fmaxf(v.x, v.y), fmaxf(v.z, v.w)));
    }
    for (int off = 16; off > 0; off >>= 1)
        m = fmaxf(m, __shfl_xor_sync(0xFFFFFFFF, m, off));

    float sum = 0.f;
#pragma unroll
    for (int i = 0; i < 16; i++) {
        float e = (vals[i] == -INFINITY) ? 0.f : __expf(vals[i] - m);
        vals[i] = e;
        sum += e;
    }
    for (int off = 16; off > 0; off >>= 1)
        sum += __shfl_xor_sync(0xFFFFFFFF, sum, off);

    float inv = (sum > 0.f) ? (1.f / sum) : 0.f;
#pragma unroll
    for (int i = 0; i < 4; i++) {
        float4 o = {vals[i * 4 + 0] * inv, vals[i * 4 + 1] * inv,
                    vals[i * 4 + 2] * inv, vals[i * 4 + 3] * inv};
        *(float4*)&probs[warp][i * 128 + lane * 4] = o;
    }
    __syncthreads();

    if (threadIdx.x < 128) {
        int s4 = threadIdx.x * 4;
        float4 a = {0.f, 0.f, 0.f, 0.f};
#pragma unroll
        for (int h = 0; h < 8; h++) {
            float4 p = *(const float4*)&probs[h][s4];
            a.x += p.x; a.y += p.y; a.z += p.z; a.w += p.w;
        }
        float4 o = {a.x * 0.125f, a.y * 0.125f, a.z * 0.125f, a.w * 0.125f};
        *(float4*)&g_attn[(size_t)bt * Sv + s4] = o;
    }
}

// ---------------- K5: fused lse + dense output + sparse scatter (R6 structure) ----------------
__global__ __launch_bounds__(512)
void lse_out_scatter_kernel(const float* __restrict__ logits,
                            const int* __restrict__ ids,
                            float* __restrict__ out) {
    int bt = blockIdx.x;
    int tid = threadIdx.x;
    const float4* row = (const float4*)(logits + (size_t)bt * Vv);
    __shared__ float ssum[16];
    __shared__ int sid[512];
    int warp = tid >> 5, lane = tid & 31;
    int b = bt / Tv;

    // pass A: S = sum exp(x)
    float s = 0.f;
    for (int i = tid; i < Vv / 4; i += 512) {
        float4 v = row[i];
        s += expp(v.x) + expp(v.y) + expp(v.z) + expp(v.w);
    }
    for (int off = 16; off > 0; off >>= 1)
        s += __shfl_xor_sync(0xFFFFFFFF, s, off);
    if (lane == 0) ssum[warp] = s;
    __syncthreads();
    float S = ssum[0];
#pragma unroll
    for (int i = 1; i < 16; i++) S += ssum[i];
    float lse = __logf(S);

    float l1m = g_log1mcp[bt];
    float lcp = g_logcp[bt];
    float p1c = LOG_EPS + lcp;
    float lnA = l1m - lse;
    float Cc  = __expf(p1c);
    float tv  = (p1c > -1e30f) ? p1c : FMINF;

    // pass B: dense write
    float4* orow = (float4*)(out + (size_t)bt * VTv);
    for (int i = tid; i < VTv / 4; i += 512) {
        float4 o;
        if (i < Vv / 4) {
            float4 v = row[i];
            o.x = __logf(expp(v.x + lnA) + Cc);
            o.y = __logf(expp(v.y + lnA) + Cc);
            o.z = __logf(expp(v.z + lnA) + Cc);
            o.w = __logf(expp(v.w + lnA) + Cc);
        } else {
            o.x = o.y = o.z = o.w = tv;
        }
        orow[i] = o;
    }

    // pass C: sparse scatter fix-up
    sid[tid] = ids[b * Sv + tid];
    __syncthreads();

    int c = g_canon[b * Sv + tid];
    if (c < 0) return;
    int id = sid[tid];

    float sum = g_attn[(size_t)bt * Sv + tid];
    if (c > 0) {
        for (int j = tid + 1; j < Sv; j++)
            if (sid[j] == id) sum += g_attn[(size_t)bt * Sv + j];
    }

    float p0;
    if (id < Vv) {
        p0 = fmaxf(logits[(size_t)bt * Vv + id] - lse + l1m, FMINF);
    } else {
        p0 = FMINF;
    }
    float plp = (sum > 0.f) ? logf(sum) : LOG_EPS;
    float p1 = plp + lcp;
    if (p1 == -INFINITY) p1 = FMINF;

    out[(size_t)bt * VTv + id] = lae(p0, p1);
}

// ---------------- launch (single stream) ----------------
extern "C" void kernel_launch(void* const* d_in, const int* in_sizes, int n_in,
                              void* d_out, int out_size) {
    const float* logits = (const float*)d_in[0];
    const int*   ids    = (const int*)d_in[1];
    const float* src    = (const float*)d_in[2];
    const void*  pad    = d_in[3];
    const float* tgt    = (const float*)d_in[4];
    const float* w_q    = (const float*)d_in[5];
    const float* b_q    = (const float*)d_in[6];
    const float* w_k    = (const float*)d_in[7];
    const float* b_k    = (const float*)d_in[8];
    const float* w_copy = (const float*)d_in[9];
    const float* b_copy = (const float*)d_in[10];
    float* out = (float*)d_out;

    cudaFuncSetAttribute(gemm_mma_kernel,
                         cudaFuncAttributeMaxDynamicSharedMemorySize, GSM);

    prep_all_kernel<<<2184, 512>>>(pad, ids, tgt, w_copy, b_copy, src, w_k, w_q);
    gemm_mma_kernel<<<dim3(8, 36), 256, GSM>>>(b_k, b_q);
    scores_kernel<<<dim3(Bv * Hv, 4), 256>>>();
    softmax_mean_kernel<<<Bv * Tv, 256>>>();
    lse_out_scatter_kernel<<<Bv * Tv, 512>>>(logits, ids, out);
}

// round 10
// speedup vs baseline: 3.8715x; 1.9483x over previous
#include <cuda_runtime.h>
#include <cuda_bf16.h>
#include <math.h>
#include <stdint.h>

#define Bv 8
#define Sv 512
#define Tv 64
#define Dv 512
#define Hv 8
#define Vv 32000
#define EVv 2048
#define VTv 34048

#define FMINF (-3.402823466e38f)
#define LOG_EPS (-15.9423847198486328125f)   /* logf(2^-23) */

// ---------------- scratch ----------------
__device__ __align__(16) float g_k[Bv*Sv*Dv];         // 8 MB
__device__ __align__(16) float g_q[Bv*Tv*Dv];         // 1 MB
__device__ __align__(16) float g_scores[Bv*Hv*Tv*Sv]; // 8 MB
__device__ __align__(16) float g_attn[Bv*Tv*Sv];      // 1 MB
__device__ float g_logcp[Bv*Tv];
__device__ float g_log1mcp[Bv*Tv];
__device__ int   g_canon[Bv*Sv];
__device__ int   g_pad_is_int;

// bf16 split copies (activations stacked: rows 0..4095 = src, 4096..4607 = tgt)
__device__ __align__(16) __nv_bfloat16 g_a_hi[4608*512];
__device__ __align__(16) __nv_bfloat16 g_a_lo[4608*512];
// transposed weights: slice 0 = w_k^T [n][k], slice 1 = w_q^T
__device__ __align__(16) __nv_bfloat16 g_wt_hi[2*512*512];
__device__ __align__(16) __nv_bfloat16 g_wt_lo[2*512*512];

// ---------------- helpers ----------------
__device__ __forceinline__ bool is_pad(const void* p, int idx) {
    if (g_pad_is_int) return ((const int*)p)[idx] != 0;
    return ((const unsigned char*)p)[idx] != 0;
}
__device__ __forceinline__ float lae(float a, float b) {
    float m = fmaxf(a, b);
    return m + log1pf(__expf(-fabsf(a - b)));
}

// fast exp on the FMA pipe (poly 2^f; rel err ~5e-5)
__device__ __forceinline__ float expp(float x) {
    x = fmaxf(x, -80.0f);
    float y = x * 1.44269504f;
    float n = rintf(y);
    float f = y - n;
    float p = 0.00961813f;
    p = fmaf(p, f, 0.05550411f);
    p = fmaf(p, f, 0.24022651f);
    p = fmaf(p, f, 0.69314718f);
    p = fmaf(p, f, 1.0f);
    float s = __int_as_float(((int)n + 127) << 23);
    return p * s;
}

__device__ __forceinline__ uint32_t smem_u32(const void* p) {
    uint32_t a;
    asm("{ .reg .u64 t; cvta.to.shared.u64 t, %1; cvt.u32.u64 %0, t; }" : "=r"(a) : "l"(p));
    return a;
}
__device__ __forceinline__ void ldsm4(uint32_t* r, uint32_t addr) {
    asm volatile("ldmatrix.sync.aligned.m8n8.x4.shared.b16 {%0,%1,%2,%3}, [%4];"
                 : "=r"(r[0]), "=r"(r[1]), "=r"(r[2]), "=r"(r[3]) : "r"(addr));
}
__device__ __forceinline__ void mma_bf16(float* d, const uint32_t* a, const uint32_t* b) {
    asm volatile(
        "mma.sync.aligned.m16n8k16.row.col.f32.bf16.bf16.f32 "
        "{%0,%1,%2,%3}, {%4,%5,%6,%7}, {%8,%9}, {%0,%1,%2,%3};"
        : "+f"(d[0]), "+f"(d[1]), "+f"(d[2]), "+f"(d[3])
        : "r"(a[0]), "r"(a[1]), "r"(a[2]), "r"(a[3]), "r"(b[0]), "r"(b[1]));
}
__device__ __forceinline__ void cpa16(uint32_t s, const void* g) {
    asm volatile("cp.async.cg.shared.global [%0], [%1], 16;" :: "r"(s), "l"(g));
}

// ---------------- K1: prep_all = sniff / canon / copygate / conv_a / conv_w ----------------
__global__ __launch_bounds__(512)
void prep_all_kernel(const void* __restrict__ pad,
                     const int* __restrict__ ids,
                     const float* __restrict__ tgt,
                     const float* __restrict__ wc,
                     const float* __restrict__ bc,
                     const float* __restrict__ src,
                     const float* __restrict__ wk,
                     const float* __restrict__ wq) {
    int bid = blockIdx.x;
    int tid = threadIdx.x;

    if (bid == 0) {
        __shared__ int bad;
        if (tid == 0) bad = 0;
        __syncthreads();
        const unsigned* w = (const unsigned*)pad;
        for (int i = tid; i < 1024; i += 512)
            if (w[i] > 1u) atomicOr(&bad, 1);
        __syncthreads();
        if (tid == 0) g_pad_is_int = bad ? 0 : 1;
        return;
    }
    if (bid <= 8) {
        int b = bid - 1;
        int s = tid;
        __shared__ int sid[512];
        sid[s] = ids[b * Sv + s];
        __syncthreads();
        int my = sid[s];
        bool canon = true;
        for (int j = 0; j < s; j++)
            if (sid[j] == my) { canon = false; break; }
        int cnt = 0;
        if (canon)
            for (int j = s + 1; j < Sv; j++) cnt += (sid[j] == my);
        g_canon[b * Sv + s] = canon ? cnt : -1;
        return;
    }
    if (bid <= 520) {
        int bt = bid - 9;
        float acc = tgt[(size_t)bt * Dv + tid] * wc[tid];
        for (int off = 16; off > 0; off >>= 1)
            acc += __shfl_xor_sync(0xFFFFFFFF, acc, off);
        __shared__ float sred[16];
        int warp = tid >> 5, lane = tid & 31;
        if (lane == 0) sred[warp] = acc;
        __syncthreads();
        if (tid == 0) {
            float z = bc[0];
            for (int i = 0; i < 16; i++) z += sred[i];
            float cp = 1.f / (1.f + expf(-z));
            g_logcp[bt]   = logf(cp);
            g_log1mcp[bt] = logf(1.f - cp);
        }
        return;
    }
    if (bid <= 1672) {
        int q = (bid - 521) * 512 + tid;
        int row = q >> 7;
        int c4  = (q & 127) * 4;
        float4 v = (row < 4096)
            ? *(const float4*)&src[(size_t)row * 512 + c4]
            : *(const float4*)&tgt[(size_t)(row - 4096) * 512 + c4];
        float xs[4] = {v.x, v.y, v.z, v.w};
        unsigned short h[4], l[4];
#pragma unroll
        for (int i = 0; i < 4; i++) {
            __nv_bfloat16 hb = __float2bfloat16(xs[i]);
            float lo = xs[i] - __bfloat162float(hb);
            h[i] = __bfloat16_as_ushort(hb);
            l[i] = __bfloat16_as_ushort(__float2bfloat16(lo));
        }
        uint2 H = {(unsigned)h[0] | ((unsigned)h[1] << 16), (unsigned)h[2] | ((unsigned)h[3] << 16)};
        uint2 L = {(unsigned)l[0] | ((unsigned)l[1] << 16), (unsigned)l[2] | ((unsigned)l[3] << 16)};
        *(uint2*)&g_a_hi[(size_t)row * 512 + c4] = H;
        *(uint2*)&g_a_lo[(size_t)row * 512 + c4] = L;
        return;
    }
    {
        int bid2 = bid - 1673;
        int z = bid2 >> 8;
        const float* W = z ? wq : wk;
        int r = bid2 & 255;
        int n0 = (r & 15) * 32, k0 = (r >> 4) * 32;
        __shared__ float tile[32][33];
        int tx = tid & 31, ty = tid >> 5;
#pragma unroll
        for (int i = 0; i < 2; i++)
            tile[ty + i * 16][tx] = W[(size_t)(k0 + ty + i * 16) * 512 + n0 + tx];
        __syncthreads();
#pragma unroll
        for (int i = 0; i < 2; i++) {
            int n = n0 + ty + i * 16;
            int k = k0 + tx;
            float x = tile[tx][ty + i * 16];
            __nv_bfloat16 hb = __float2bfloat16(x);
            float lo = x - __bfloat162float(hb);
            size_t o = (size_t)z * 262144 + (size_t)n * 512 + k;
            g_wt_hi[o] = hb;
            g_wt_lo[o] = __float2bfloat16(lo);
        }
    }
}

// ---------------- K2: HMMA dual GEMM, 3-stage cp.async, K_CHUNK=32 ----------------
#define STG_A_LO 10240
#define STG_B_HI 20480
#define STG_B_LO 25600
#define STG_SZ   30720
#define GSM (3 * STG_SZ)

__global__ __launch_bounds__(256)
void gemm_mma_kernel(const float* __restrict__ b_k, const float* __restrict__ b_q) {
    extern __shared__ __align__(16) char sm[];
    int tid = threadIdx.x;
    int lane = tid & 31;
    int wid = tid >> 5;
    int wm = wid & 3, wn = wid >> 2;

    int yb = blockIdx.y;
    bool isQ = (yb >= 32);
    int arow0 = isQ ? 4096 + (yb - 32) * 128 : yb * 128;
    int orow0 = isQ ? (yb - 32) * 128 : yb * 128;
    float* C = isQ ? g_q : g_k;
    const float* bias = isQ ? b_q : b_k;
    int n0 = blockIdx.x * 64;
    size_t wtb = (isQ ? (size_t)262144 : 0) + (size_t)n0 * 512;

    uint32_t sbase = smem_u32(sm);

    auto issue_chunk = [&](int kc, int st) {
        uint32_t sb = sbase + st * STG_SZ;
#pragma unroll
        for (int i = 0; i < 2; i++) {
            int idx = tid + i * 256;
            int r = idx >> 2, c = idx & 3;
            size_t gg = (size_t)(arow0 + r) * 512 + kc * 32 + c * 8;
            uint32_t d = (uint32_t)(r * 80 + c * 16);
            cpa16(sb + d, &g_a_hi[gg]);
            cpa16(sb + STG_A_LO + d, &g_a_lo[gg]);
        }
        {
            int r = tid >> 2, c = tid & 3;
            size_t gg = wtb + (size_t)r * 512 + kc * 32 + c * 8;
            uint32_t d = (uint32_t)(r * 80 + c * 16);
            cpa16(sb + STG_B_HI + d, &g_wt_hi[gg]);
            cpa16(sb + STG_B_LO + d, &g_wt_lo[gg]);
        }
        asm volatile("cp.async.commit_group;" ::: "memory");
    };

    int a_row = (lane & 7) + ((lane >> 3) & 1) * 8;
    int a_k8  = (lane >> 4) * 8;
    int b_row = (lane & 7) + (lane >> 4) * 8;
    int b_k8  = ((lane >> 3) & 1) * 8;

    float acc[2][4][4] = {};

    issue_chunk(0, 0);
    issue_chunk(1, 1);

#pragma unroll 1
    for (int kc = 0; kc < 16; kc++) {
        if (kc < 14) asm volatile("cp.async.wait_group 1;" ::: "memory");
        else         asm volatile("cp.async.wait_group 0;" ::: "memory");
        __syncthreads();
        if (kc + 2 < 16) issue_chunk(kc + 2, (kc + 2) % 3);

        uint32_t cb = sbase + (uint32_t)((kc % 3) * STG_SZ);
        uint32_t aB = cb + (uint32_t)(wm * 32 + a_row) * 80 + a_k8 * 2;
        uint32_t bB = cb + STG_B_HI + (uint32_t)(wn * 32 + b_row) * 80 + b_k8 * 2;

#pragma unroll
        for (int ks = 0; ks < 2; ks++) {
            uint32_t bh0[4], bh1[4], bl0[4], bl1[4];
            uint32_t ba = bB + ks * 32;
            ldsm4(bh0, ba);
            ldsm4(bh1, ba + 16 * 80);
            ldsm4(bl0, ba + (STG_B_LO - STG_B_HI));
            ldsm4(bl1, ba + (STG_B_LO - STG_B_HI) + 16 * 80);
#pragma unroll
            for (int mt = 0; mt < 2; mt++) {
                uint32_t ah[4], al[4];
                uint32_t aa = aB + (uint32_t)(mt * 16) * 80 + ks * 32;
                ldsm4(ah, aa);
                ldsm4(al, aa + STG_A_LO);
                mma_bf16(acc[mt][0], ah, bh0);
                mma_bf16(acc[mt][0], ah, bl0);
                mma_bf16(acc[mt][0], al, bh0);
                mma_bf16(acc[mt][1], ah, bh0 + 2);
                mma_bf16(acc[mt][1], ah, bl0 + 2);
                mma_bf16(acc[mt][1], al, bh0 + 2);
                mma_bf16(acc[mt][2], ah, bh1);
                mma_bf16(acc[mt][2], ah, bl1);
                mma_bf16(acc[mt][2], al, bh1);
                mma_bf16(acc[mt][3], ah, bh1 + 2);
                mma_bf16(acc[mt][3], ah, bl1 + 2);
                mma_bf16(acc[mt][3], al, bh1 + 2);
            }
        }
    }

    // epilogue
    int g = lane >> 2, t4 = lane & 3;
#pragma unroll
    for (int mt = 0; mt < 2; mt++) {
#pragma unroll
        for (int nt = 0; nt < 4; nt++) {
            int col = n0 + wn * 32 + nt * 8 + t4 * 2;
            float2 bb = *(const float2*)&bias[col];
            int row0 = orow0 + wm * 32 + mt * 16 + g;
            float2 v0 = {acc[mt][nt][0] + bb.x, acc[mt][nt][1] + bb.y};
            float2 v1 = {acc[mt][nt][2] + bb.x, acc[mt][nt][3] + bb.y};
            *(float2*)&C[(size_t)row0 * 512 + col] = v0;
            *(float2*)&C[(size_t)(row0 + 8) * 512 + col] = v1;
        }
    }
}

// ---------------- K3: scores — register-tiled 64x512x64 SGEMM per (b,h,squarter) ----------------
__global__ __launch_bounds__(128)
void scores_kernel() {
    __shared__ __align__(16) float kT[64][128];  // [d][s]
    __shared__ __align__(16) float qT[64][72];   // [d][t], padded
    int bh = blockIdx.x;
    int b = bh >> 3, h = bh & 7;
    int s0 = blockIdx.y * 128;
    int tid = threadIdx.x;

    {
        int s = tid;
        const float* kp = &g_k[((size_t)(b * Sv + s0 + s)) * Dv + h * 64];
#pragma unroll
        for (int j = 0; j < 16; j++) {
            float4 v = *(const float4*)&kp[j * 4];
            kT[j * 4 + 0][s] = v.x;
            kT[j * 4 + 1][s] = v.y;
            kT[j * 4 + 2][s] = v.z;
            kT[j * 4 + 3][s] = v.w;
        }
    }
    {
        int t = tid & 63, dh = tid >> 6;
        const float* qp = &g_q[((size_t)(b * Tv + t)) * Dv + h * 64 + dh * 32];
#pragma unroll
        for (int j = 0; j < 8; j++) {
            float4 v = *(const float4*)&qp[j * 4];
            int d = dh * 32 + j * 4;
            qT[d + 0][t] = v.x;
            qT[d + 1][t] = v.y;
            qT[d + 2][t] = v.z;
            qT[d + 3][t] = v.w;
        }
    }
    __syncthreads();

    int tx = tid & 15, ty = tid >> 4;
    float acc[8][8] = {};
#pragma unroll
    for (int kk = 0; kk < 64; kk++) {
        float4 a0 = *(const float4*)&qT[kk][ty * 8];
        float4 a1 = *(const float4*)&qT[kk][ty * 8 + 4];
        float4 b0 = *(const float4*)&kT[kk][tx * 8];
        float4 b1 = *(const float4*)&kT[kk][tx * 8 + 4];
        float av[8] = {a0.x, a0.y, a0.z, a0.w, a1.x, a1.y, a1.z, a1.w};
        float bv[8] = {b0.x, b0.y, b0.z, b0.w, b1.x, b1.y, b1.z, b1.w};
#pragma unroll
        for (int i = 0; i < 8; i++)
#pragma unroll
            for (int j = 0; j < 8; j++)
                acc[i][j] += av[i] * bv[j];
    }

    float* op = &g_scores[(((size_t)(b * Hv + h)) * Tv) * Sv + s0];
#pragma unroll
    for (int i = 0; i < 8; i++) {
        int t = ty * 8 + i;
#pragma unroll
        for (int j = 0; j < 2; j++) {
            float4 o = {acc[i][j * 4 + 0] * 0.125f, acc[i][j * 4 + 1] * 0.125f,
                        acc[i][j * 4 + 2] * 0.125f, acc[i][j * 4 + 3] * 0.125f};
            *(float4*)&op[(size_t)t * Sv + tx * 8 + j * 4] = o;
        }
    }
}

// ---------------- K4: masked softmax per head + mean over heads ----------------
__global__ __launch_bounds__(256)
void softmax_mean_kernel(const void* __restrict__ pad) {
    int bt = blockIdx.x;
    int b = bt / Tv, t = bt % Tv;
    int warp = threadIdx.x >> 5, lane = threadIdx.x & 31;

    __shared__ float probs[8][512];

    const float* sc = &g_scores[(((size_t)b * Hv + warp) * Tv + t) * Sv];
    float vals[16];
    float m = -INFINITY;
#pragma unroll
    for (int i = 0; i < 16; i++) {
        int s = lane + 32 * i;
        float v = is_pad(pad, b * Sv + s) ? -INFINITY : sc[s];
        vals[i] = v;
        m = fmaxf(m, v);
    }
    for (int off = 16; off > 0; off >>= 1)
        m = fmaxf(m, __shfl_xor_sync(0xFFFFFFFF, m, off));

    float sum = 0.f;
#pragma unroll
    for (int i = 0; i < 16; i++) {
        float e = (vals[i] == -INFINITY) ? 0.f : __expf(vals[i] - m);
        vals[i] = e;
        sum += e;
    }
    for (int off = 16; off > 0; off >>= 1)
        sum += __shfl_xor_sync(0xFFFFFFFF, sum, off);

    float inv = (sum > 0.f) ? (1.f / sum) : 0.f;
#pragma unroll
    for (int i = 0; i < 16; i++)
        probs[warp][lane + 32 * i] = vals[i] * inv;
    __syncthreads();

    for (int s = threadIdx.x; s < Sv; s += 256) {
        float a = 0.f;
#pragma unroll
        for (int h = 0; h < 8; h++) a += probs[h][s];
        g_attn[(size_t)bt * Sv + s] = a * 0.125f;
    }
}

// ---------------- K5: fused lse + dense output + sparse scatter fix-up ----------------
__global__ __launch_bounds__(512)
void lse_out_scatter_kernel(const float* __restrict__ logits,
                            const int* __restrict__ ids,
                            float* __restrict__ out) {
    int bt = blockIdx.x;
    int tid = threadIdx.x;
    const float4* row = (const float4*)(logits + (size_t)bt * Vv);
    __shared__ float ssum[16];
    __shared__ int sid[512];
    int warp = tid >> 5, lane = tid & 31;
    int b = bt / Tv;

    // pass A: S = sum exp(x)
    float s = 0.f;
    for (int i = tid; i < Vv / 4; i += 512) {
        float4 v = row[i];
        s += expp(v.x) + expp(v.y) + expp(v.z) + expp(v.w);
    }
    for (int off = 16; off > 0; off >>= 1)
        s += __shfl_xor_sync(0xFFFFFFFF, s, off);
    if (lane == 0) ssum[warp] = s;
    __syncthreads();
    float S = ssum[0];
#pragma unroll
    for (int i = 1; i < 16; i++) S += ssum[i];
    float lse = __logf(S);

    float l1m = g_log1mcp[bt];
    float lcp = g_logcp[bt];
    float p1c = LOG_EPS + lcp;
    float lnA = l1m - lse;
    float Cc  = __expf(p1c);
    float tv  = (p1c > -1e30f) ? p1c : FMINF;

    // pass B: dense write
    float4* orow = (float4*)(out + (size_t)bt * VTv);
    for (int i = tid; i < VTv / 4; i += 512) {
        float4 o;
        if (i < Vv / 4) {
            float4 v = row[i];
            o.x = __logf(expp(v.x + lnA) + Cc);
            o.y = __logf(expp(v.y + lnA) + Cc);
            o.z = __logf(expp(v.z + lnA) + Cc);
            o.w = __logf(expp(v.w + lnA) + Cc);
        } else {
            o.x = o.y = o.z = o.w = tv;
        }
        orow[i] = o;
    }

    // pass C: sparse scatter fix-up
    sid[tid] = ids[b * Sv + tid];
    __syncthreads();

    int c = g_canon[b * Sv + tid];
    if (c < 0) return;
    int id = sid[tid];

    float sum = g_attn[(size_t)bt * Sv + tid];
    if (c > 0) {
        for (int j = tid + 1; j < Sv; j++)
            if (sid[j] == id) sum += g_attn[(size_t)bt * Sv + j];
    }

    float p0;
    if (id < Vv) {
        p0 = fmaxf(logits[(size_t)bt * Vv + id] - lse + l1m, FMINF);
    } else {
        p0 = FMINF;
    }
    float plp = (sum > 0.f) ? logf(sum) : LOG_EPS;
    float p1 = plp + lcp;
    if (p1 == -INFINITY) p1 = FMINF;

    out[(size_t)bt * VTv + id] = lae(p0, p1);
}

// ---------------- launch ----------------
extern "C" void kernel_launch(void* const* d_in, const int* in_sizes, int n_in,
                              void* d_out, int out_size) {
    const float* logits = (const float*)d_in[0];
    const int*   ids    = (const int*)d_in[1];
    const float* src    = (const float*)d_in[2];
    const void*  pad    = d_in[3];
    const float* tgt    = (const float*)d_in[4];
    const float* w_q    = (const float*)d_in[5];
    const float* b_q    = (const float*)d_in[6];
    const float* w_k    = (const float*)d_in[7];
    const float* b_k    = (const float*)d_in[8];
    const float* w_copy = (const float*)d_in[9];
    const float* b_copy = (const float*)d_in[10];
    float* out = (float*)d_out;

    static bool inited = false;
    if (!inited) {
        cudaFuncSetAttribute(gemm_mma_kernel,
                             cudaFuncAttributeMaxDynamicSharedMemorySize, GSM);
        inited = true;
    }

    prep_all_kernel<<<2185, 512>>>(pad, ids, tgt, w_copy, b_copy, src, w_k, w_q);
    gemm_mma_kernel<<<dim3(8, 36), 256, GSM>>>(b_k, b_q);
    scores_kernel<<<dim3(Bv * Hv, 4), 128>>>();
    softmax_mean_kernel<<<Bv * Tv, 256>>>(pad);
    lse_out_scatter_kernel<<<Bv * Tv, 512>>>(logits, ids, out);
}